// round 3
// baseline (speedup 1.0000x reference)
#include <cuda_runtime.h>
#include <cuda_bf16.h>
#include <math.h>

// Problem constants
#define Fn 500
#define Hn 2000
#define FH 2500      // F + H
#define Dn 64
#define An 64
#define Bn 4096
#define NB 148       // persistent grid: one wave, <= SM count

// Scratch (device globals; no allocation allowed)
__device__ float g_pre_f[Fn * Dn];
__device__ float g_pre_w[FH * Dn];
__device__ float g_full [FH * Dn];
__device__ float g_ctx  [Fn * Dn];
__device__ float g_pwmax[FH];

// Device-wide barrier state (replay-safe: count self-resets, gen monotonic)
__device__ unsigned g_count = 0;
__device__ unsigned g_gen   = 0;

__device__ __forceinline__ void grid_bar() {
    __syncthreads();
    if (threadIdx.x == 0) {
        __threadfence();
        unsigned gen = atomicAdd(&g_gen, 0u);
        __threadfence();
        if (atomicAdd(&g_count, 1u) == NB - 1u) {
            g_count = 0u;
            __threadfence();
            atomicAdd(&g_gen, 1u);
        } else {
            while (atomicAdd(&g_gen, 0u) == gen) __nanosleep(32);
        }
    }
    __syncthreads();
}

// ---------------- packed f32x2 helpers (Blackwell) ----------------
__device__ __forceinline__ unsigned long long pk2(float a, float b) {
    unsigned long long r;
    asm("mov.b64 %0, {%1,%2};" : "=l"(r) : "f"(a), "f"(b));
    return r;
}
__device__ __forceinline__ void upk2(unsigned long long v, float& a, float& b) {
    asm("mov.b64 {%0,%1}, %2;" : "=f"(a), "=f"(b) : "l"(v));
}
__device__ __forceinline__ unsigned long long f2fma(unsigned long long a,
                                                    unsigned long long b,
                                                    unsigned long long c) {
    unsigned long long d;
    asm("fma.rn.f32x2 %0, %1, %2, %3;" : "=l"(d) : "l"(a), "l"(b), "l"(c));
    return d;
}
__device__ __forceinline__ unsigned long long f2add(unsigned long long a,
                                                    unsigned long long b) {
    unsigned long long d;
    asm("add.rn.f32x2 %0, %1, %2;" : "=l"(d) : "l"(a), "l"(b));
    return d;
}
__device__ __forceinline__ unsigned long long f2mul(unsigned long long a,
                                                    unsigned long long b) {
    unsigned long long d;
    asm("mul.rn.f32x2 %0, %1, %2;" : "=l"(d) : "l"(a), "l"(b));
    return d;
}

// ---------------- shared memory union across stages ----------------
#define TFk 50
struct S1 {                       // stage 1: projections
    float W[128 * 64];            // Ww cached (32KB)
    float sx[4][Dn];
    float m[8];
};
struct S2 {                       // stage 2: masked attention
    int   jlist[FH];
    float elist[FH];
    int   warpbase[9];
    float wsum[8];
    float pf[Dn];
    float wu[Dn];
    float part[4][Dn];
    float pfmax;
    float inv;
};
struct S3 {                       // stage 3: out gemm
    float val[32][TFk];
    float ctx[TFk][Dn];
};
union SMem { S1 s1; S2 s2; S3 s3; };

// ---------------------------------------------------------------------------
__global__ __launch_bounds__(256) void fused_all(
    const float* __restrict__ values,
    const float* __restrict__ feat,
    const float* __restrict__ hid,
    const float* __restrict__ Ww,
    const float* __restrict__ bw,
    const float* __restrict__ Wu,
    const float* __restrict__ mask,
    float* __restrict__ out)
{
    __shared__ SMem sm;
    const int tid  = threadIdx.x;
    const int wid  = tid >> 5;
    const int lane = tid & 31;

    // ===================== Stage 1: pre_f / pre_w / full =====================
    {
        for (int idx = tid; idx < 128 * 64; idx += 256)
            sm.s1.W[idx] = Ww[idx];
        __syncthreads();

        const int g = tid >> 6;   // row-in-task 0..3
        const int a = tid & 63;   // output column

        for (int t = blockIdx.x; t < 750; t += NB) {
            if (t < 625) {
                const int row = t * 4 + g;               // 0..2499
                float v = (row < Fn) ? feat[row * Dn + a]
                                     : hid[(row - Fn) * Dn + a];
                g_full[row * Dn + a] = v;
                sm.s1.sx[g][a] = v;
                __syncthreads();
                float acc = 0.f;
                #pragma unroll
                for (int k = 0; k < Dn; k++)
                    acc += sm.s1.sx[g][k] * sm.s1.W[(Dn + k) * An + a];  // W2
                g_pre_w[row * Dn + a] = acc;
                float mm = fabsf(acc);
                #pragma unroll
                for (int off = 16; off > 0; off >>= 1)
                    mm = fmaxf(mm, __shfl_xor_sync(0xffffffffu, mm, off));
                if (lane == 0) sm.s1.m[wid] = mm;
                __syncthreads();
                if (tid < 4)
                    g_pwmax[t * 4 + tid] =
                        fmaxf(sm.s1.m[2 * tid], sm.s1.m[2 * tid + 1]);
                __syncthreads();
            } else {
                const int row = (t - 625) * 4 + g;       // 0..499
                sm.s1.sx[g][a] = feat[row * Dn + a];
                __syncthreads();
                float acc = bw[a];
                #pragma unroll
                for (int k = 0; k < Dn; k++)
                    acc += sm.s1.sx[g][k] * sm.s1.W[k * An + a];         // W1
                g_pre_f[row * Dn + a] = acc;
                __syncthreads();
            }
        }
    }

    grid_bar();

    // ===================== Stage 2: masked attention -> ctx ==================
    for (int i = blockIdx.x; i < Fn; i += NB) {
        if (tid < Dn) {
            sm.s2.pf[tid] = g_pre_f[i * Dn + tid];
            sm.s2.wu[tid] = Wu[tid];
        }
        __syncthreads();

        if (wid == 0) {
            float m = fmaxf(fabsf(sm.s2.pf[lane]), fabsf(sm.s2.pf[lane + 32]));
            #pragma unroll
            for (int off = 16; off > 0; off >>= 1)
                m = fmaxf(m, __shfl_xor_sync(0xffffffffu, m, off));
            if (lane == 0) sm.s2.pfmax = m;
        }

        // ---- Phase A: single-pass deterministic compaction
        const float* mrow = mask + (size_t)i * FH;
        unsigned flags = 0;
        #pragma unroll
        for (int c = 0; c < 10; c++) {
            int j = c * 256 + tid;
            if (j < FH && mrow[j] != 0.0f) flags |= (1u << c);
        }
        const int cl = __popc(flags);
        int inc = cl;
        #pragma unroll
        for (int off = 1; off < 32; off <<= 1) {
            int v = __shfl_up_sync(0xffffffffu, inc, off);
            if (lane >= off) inc += v;
        }
        if (lane == 31) sm.s2.warpbase[wid + 1] = inc;
        __syncthreads();
        if (tid == 0) {
            sm.s2.warpbase[0] = 0;
            #pragma unroll
            for (int w = 1; w <= 8; w++)
                sm.s2.warpbase[w] += sm.s2.warpbase[w - 1];
        }
        __syncthreads();
        {
            int off = sm.s2.warpbase[wid] + inc - cl;
            #pragma unroll
            for (int c = 0; c < 10; c++)
                if ((flags >> c) & 1u) sm.s2.jlist[off++] = c * 256 + tid;
        }
        __syncthreads();
        const int cnt = sm.s2.warpbase[8];

        // ---- Phase B: warp-per-item packed tanh-dot + exp
        const float pf0 = sm.s2.pf[2 * lane], pf1 = sm.s2.pf[2 * lane + 1];
        const float wu0 = sm.s2.wu[2 * lane], wu1 = sm.s2.wu[2 * lane + 1];
        const unsigned long long pfp = pk2(pf0, pf1);
        const unsigned long long wup = pk2(wu0, wu1);
        const unsigned long long C3  = pk2(-0.33333334f, -0.33333334f);
        const unsigned long long C5  = pk2( 0.13333334f,  0.13333334f);
        const unsigned long long C7  = pk2(-0.05396825f, -0.05396825f);
        const unsigned long long ONE = pk2(1.0f, 1.0f);
        const float pfmax = sm.s2.pfmax;
        float wsum = 0.f;

        for (int m = wid; m < cnt; m += 8) {
            const int j = sm.s2.jlist[m];
            const float2 pw = __ldg(((const float2*)(g_pre_w + j * Dn)) + lane);
            float s;
            if (pfmax + __ldg(&g_pwmax[j]) > 0.45f) {
                s = tanhf(pf0 + pw.x) * wu0 + tanhf(pf1 + pw.y) * wu1;
            } else {
                unsigned long long xp = f2add(pfp, pk2(pw.x, pw.y));
                unsigned long long t  = f2mul(xp, xp);
                unsigned long long p  = f2fma(t, C7, C5);
                p = f2fma(t, p, C3);
                p = f2fma(t, p, ONE);
                unsigned long long y   = f2mul(xp, p);
                unsigned long long acc = f2mul(y, wup);
                float a0, a1; upk2(acc, a0, a1);
                s = a0 + a1;
            }
            #pragma unroll
            for (int off = 16; off > 0; off >>= 1)
                s += __shfl_xor_sync(0xffffffffu, s, off);
            if (lane == 0) {
                float e = expf(s);
                sm.s2.elist[m] = e;
                wsum += e;
            }
        }
        if (lane == 0) sm.s2.wsum[wid] = wsum;
        __syncthreads();
        if (tid == 0) {
            float ss = 0.f;
            #pragma unroll
            for (int w = 0; w < 8; w++) ss += sm.s2.wsum[w];
            sm.s2.inv = (ss > 0.f) ? (1.0f / ss) : 1.0f;
        }
        __syncthreads();

        // ---- Phase C: context accumulation
        {
            const int g = tid >> 6;
            const int k = tid & 63;
            float acc = 0.f;
            for (int m = g; m < cnt; m += 4)
                acc += sm.s2.elist[m] * __ldg(&g_full[sm.s2.jlist[m] * Dn + k]);
            sm.s2.part[g][k] = acc;
            __syncthreads();
            if (tid < Dn)
                g_ctx[i * Dn + tid] = (sm.s2.part[0][tid] + sm.s2.part[1][tid] +
                                       sm.s2.part[2][tid] + sm.s2.part[3][tid]) *
                                      sm.s2.inv;
            __syncthreads();
        }
    }

    grid_bar();

    // ===================== Stage 3: out = values @ ctx =======================
    if (blockIdx.x < 128) {
        const int tx   = tid & 15;
        const int ty   = tid >> 4;
        const int col0 = tx * 4;
        const int row0 = blockIdx.x * 32;
        const int r0   = ty * 2;

        unsigned long long a00 = 0ull, a01 = 0ull, a10 = 0ull, a11 = 0ull;

        for (int f0 = 0; f0 < Fn; f0 += TFk) {
            for (int idx = tid; idx < 32 * TFk; idx += 256) {
                int r = idx / TFk, f = idx % TFk;
                sm.s3.val[r][f] = values[(size_t)(row0 + r) * Fn + f0 + f];
            }
            for (int idx = tid; idx < TFk * Dn; idx += 256) {
                int f = idx >> 6, c = idx & 63;
                sm.s3.ctx[f][c] = g_ctx[(f0 + f) * Dn + c];
            }
            __syncthreads();

            #pragma unroll
            for (int f = 0; f < TFk; f++) {
                float v0 = sm.s3.val[r0][f];
                float v1 = sm.s3.val[r0 + 1][f];
                unsigned long long vp0 = pk2(v0, v0);
                unsigned long long vp1 = pk2(v1, v1);
                const unsigned long long* cp =
                    reinterpret_cast<const unsigned long long*>(&sm.s3.ctx[f][col0]);
                unsigned long long c01 = cp[0];
                unsigned long long c23 = cp[1];
                a00 = f2fma(vp0, c01, a00);
                a01 = f2fma(vp0, c23, a01);
                a10 = f2fma(vp1, c01, a10);
                a11 = f2fma(vp1, c23, a11);
            }
            __syncthreads();
        }

        float a, b, c, d;
        upk2(a00, a, b); upk2(a01, c, d);
        *reinterpret_cast<float4*>(&out[(size_t)(row0 + r0) * Dn + col0]) =
            make_float4(a, b, c, d);
        upk2(a10, a, b); upk2(a11, c, d);
        *reinterpret_cast<float4*>(&out[(size_t)(row0 + r0 + 1) * Dn + col0]) =
            make_float4(a, b, c, d);
    }
}

// ---------------------------------------------------------------------------
extern "C" void kernel_launch(void* const* d_in, const int* in_sizes, int n_in,
                              void* d_out, int out_size)
{
    const float* values   = (const float*)d_in[0];   // [4096,500]
    const float* feat_emb = (const float*)d_in[1];   // [500,64]
    const float* hid_emb  = (const float*)d_in[2];   // [2000,64]
    const float* Ww       = (const float*)d_in[3];   // [128,64]
    const float* bw       = (const float*)d_in[4];   // [64]
    const float* Wu       = (const float*)d_in[5];   // [64,1]
    const float* mask     = (const float*)d_in[6];   // [500,2500,1]
    float* out            = (float*)d_out;           // [4096,64]

    fused_all<<<NB, 256>>>(values, feat_emb, hid_emb, Ww, bw, Wu, mask, out);
}

// round 5
// speedup vs baseline: 1.6235x; 1.6235x over previous
#include <cuda_runtime.h>
#include <cuda_bf16.h>
#include <math.h>

// Problem constants
#define Fn 500
#define Hn 2000
#define FH 2500      // F + H
#define Dn 64
#define An 64
#define Bn 4096

// Scratch (device globals; no allocation allowed). 16B-aligned: vector loads.
__device__ __align__(16) float g_pre_f[Fn * Dn];
__device__ __align__(16) float g_pre_w[FH * Dn];
__device__ __align__(16) float g_full [FH * Dn];
__device__ __align__(16) float g_ctx  [Fn * Dn];
__device__ float g_pwmax[FH];

// ---------------- packed f32x2 helpers (Blackwell) ----------------
__device__ __forceinline__ unsigned long long pk2(float a, float b) {
    unsigned long long r;
    asm("mov.b64 %0, {%1,%2};" : "=l"(r) : "f"(a), "f"(b));
    return r;
}
__device__ __forceinline__ void upk2(unsigned long long v, float& a, float& b) {
    asm("mov.b64 {%0,%1}, %2;" : "=f"(a), "=f"(b) : "l"(v));
}
__device__ __forceinline__ unsigned long long f2fma(unsigned long long a,
                                                    unsigned long long b,
                                                    unsigned long long c) {
    unsigned long long d;
    asm("fma.rn.f32x2 %0, %1, %2, %3;" : "=l"(d) : "l"(a), "l"(b), "l"(c));
    return d;
}
__device__ __forceinline__ unsigned long long f2add(unsigned long long a,
                                                    unsigned long long b) {
    unsigned long long d;
    asm("add.rn.f32x2 %0, %1, %2;" : "=l"(d) : "l"(a), "l"(b));
    return d;
}
__device__ __forceinline__ unsigned long long f2mul(unsigned long long a,
                                                    unsigned long long b) {
    unsigned long long d;
    asm("mul.rn.f32x2 %0, %1, %2;" : "=l"(d) : "l"(a), "l"(b));
    return d;
}

// ---------------------------------------------------------------------------
// Kernel 1: pre_w = full@W2 (+ row max|.|), pre_f = feat@W1 + bw.
// 16 rows per block, W half cached in smem once per block.
// Blocks 0..156 -> pre_w rows, 157..188 -> pre_f rows.
// ---------------------------------------------------------------------------
__global__ __launch_bounds__(256) void k1_preproj(const float* __restrict__ feat,
                                                  const float* __restrict__ hid,
                                                  const float* __restrict__ Ww,
                                                  const float* __restrict__ bw)
{
    __shared__ __align__(16) float sW[64 * 64];
    __shared__ __align__(16) float sx[16][64];
    __shared__ float s_m[8][4];

    const int b    = blockIdx.x;
    const int tid  = threadIdx.x;
    const int g    = tid >> 6;     // 0..3
    const int a    = tid & 63;     // output column
    const int wid  = tid >> 5;
    const int lane = tid & 31;

    if (b < 157) {
        const int base = b * 16;
        // cache W2 (rows 64..127 of Ww)
        for (int idx = tid; idx < 4096; idx += 256)
            sW[idx] = Ww[4096 + idx];
        // load 16 input rows (+ write g_full)
        for (int idx = tid; idx < 1024; idx += 256) {
            int r = idx >> 6, c = idx & 63;
            int row = base + r;
            float v = 0.f;
            if (row < FH) {
                v = (row < Fn) ? feat[row * Dn + c] : hid[(row - Fn) * Dn + c];
                g_full[row * Dn + c] = v;
            }
            sx[r][c] = v;
        }
        __syncthreads();

        #pragma unroll
        for (int q = 0; q < 4; q++) {
            const int r = q * 4 + g;
            const int row = base + r;
            float acc0 = 0.f, acc1 = 0.f;
            #pragma unroll
            for (int k = 0; k < 64; k += 2) {
                acc0 = fmaf(sx[r][k],     sW[k * 64 + a],       acc0);
                acc1 = fmaf(sx[r][k + 1], sW[(k + 1) * 64 + a], acc1);
            }
            float acc = acc0 + acc1;
            if (row < FH) g_pre_w[row * Dn + a] = acc;
            float mm = fabsf(acc);
            #pragma unroll
            for (int off = 16; off > 0; off >>= 1)
                mm = fmaxf(mm, __shfl_xor_sync(0xffffffffu, mm, off));
            if (lane == 0) s_m[wid][q] = mm;
        }
        __syncthreads();
        if (tid < 16) {
            int q2 = tid >> 2, g2 = tid & 3;
            int row = base + q2 * 4 + g2;
            if (row < FH)
                g_pwmax[row] = fmaxf(s_m[2 * g2][q2], s_m[2 * g2 + 1][q2]);
        }
    } else {
        const int base = (b - 157) * 16;
        for (int idx = tid; idx < 4096; idx += 256)
            sW[idx] = Ww[idx];                       // W1
        for (int idx = tid; idx < 1024; idx += 256) {
            int r = idx >> 6, c = idx & 63;
            int row = base + r;
            sx[r][c] = (row < Fn) ? feat[row * Dn + c] : 0.f;
        }
        __syncthreads();
        const float bwa = bw[a];
        #pragma unroll
        for (int q = 0; q < 4; q++) {
            const int r = q * 4 + g;
            const int row = base + r;
            float acc0 = bwa, acc1 = 0.f;
            #pragma unroll
            for (int k = 0; k < 64; k += 2) {
                acc0 = fmaf(sx[r][k],     sW[k * 64 + a],       acc0);
                acc1 = fmaf(sx[r][k + 1], sW[(k + 1) * 64 + a], acc1);
            }
            if (row < Fn) g_pre_f[row * Dn + a] = acc0 + acc1;
        }
    }
}

// ---------------------------------------------------------------------------
// Kernel 2: masked attention -> context[i,:]. One block per i, 256 threads.
// Phase B: half-warp per item (16 lanes x float4), 4-shfl reduce, predicated.
// ---------------------------------------------------------------------------
__global__ __launch_bounds__(256) void k2_attn(const float* __restrict__ mask,
                                               const float* __restrict__ Wu)
{
    __shared__ float          s_elist[FH];
    __shared__ unsigned short s_jlist[FH];
    __shared__ __align__(16) float s_pf[Dn];
    __shared__ __align__(16) float s_wu[Dn];
    __shared__ int   s_warpbase[9];
    __shared__ float s_wsum[8];
    __shared__ float s_part[4][Dn];
    __shared__ float s_pfmax;
    __shared__ float s_inv;

    const int i    = blockIdx.x;
    const int tid  = threadIdx.x;
    const int wid  = tid >> 5;
    const int lane = tid & 31;

    if (tid < Dn) {
        s_pf[tid] = g_pre_f[i * Dn + tid];
        s_wu[tid] = Wu[tid];
    }
    __syncthreads();

    if (wid == 0) {
        float m = fmaxf(fabsf(s_pf[lane]), fabsf(s_pf[lane + 32]));
        #pragma unroll
        for (int off = 16; off > 0; off >>= 1)
            m = fmaxf(m, __shfl_xor_sync(0xffffffffu, m, off));
        if (lane == 0) s_pfmax = m;
    }

    // ---- Phase A: single-pass deterministic compaction
    const float* mrow = mask + (size_t)i * FH;
    unsigned flags = 0;
    #pragma unroll
    for (int c = 0; c < 10; c++) {
        int j = c * 256 + tid;
        if (j < FH && mrow[j] != 0.0f) flags |= (1u << c);
    }
    const int cl = __popc(flags);
    int inc = cl;
    #pragma unroll
    for (int off = 1; off < 32; off <<= 1) {
        int v = __shfl_up_sync(0xffffffffu, inc, off);
        if (lane >= off) inc += v;
    }
    if (lane == 31) s_warpbase[wid + 1] = inc;
    __syncthreads();
    if (tid == 0) {
        s_warpbase[0] = 0;
        #pragma unroll
        for (int w = 1; w <= 8; w++) s_warpbase[w] += s_warpbase[w - 1];
    }
    __syncthreads();
    {
        int off = s_warpbase[wid] + inc - cl;
        #pragma unroll
        for (int c = 0; c < 10; c++)
            if ((flags >> c) & 1u)
                s_jlist[off++] = (unsigned short)(c * 256 + tid);
    }
    __syncthreads();
    const int cnt = s_warpbase[8];

    // ---- Phase B: half-warp per item
    const int half  = lane >> 4;       // 0/1
    const int lane4 = lane & 15;
    const float4 pf4 = ((const float4*)s_pf)[lane4];
    const float4 wu4 = ((const float4*)s_wu)[lane4];
    const unsigned long long pfp01 = pk2(pf4.x, pf4.y);
    const unsigned long long pfp23 = pk2(pf4.z, pf4.w);
    const unsigned long long wup01 = pk2(wu4.x, wu4.y);
    const unsigned long long wup23 = pk2(wu4.z, wu4.w);
    const unsigned long long C3  = pk2(-0.33333334f, -0.33333334f);
    const unsigned long long C5  = pk2( 0.13333334f,  0.13333334f);
    const unsigned long long C7  = pk2(-0.05396825f, -0.05396825f);
    const unsigned long long ONE = pk2(1.0f, 1.0f);
    const float pfmax = s_pfmax;
    float wsum = 0.f;

    #pragma unroll 2
    for (int base = wid * 2; base < cnt; base += 16) {
        const int  mb    = base + half;
        const bool valid = (mb < cnt);
        const int  m_s   = valid ? mb : (cnt - 1);
        const int  j     = s_jlist[m_s];
        const float4 pw  = __ldg(((const float4*)(g_pre_w + j * Dn)) + lane4);
        float s;
        if (pfmax + __ldg(&g_pwmax[j]) > 0.45f) {
            s = tanhf(pf4.x + pw.x) * wu4.x + tanhf(pf4.y + pw.y) * wu4.y +
                tanhf(pf4.z + pw.z) * wu4.z + tanhf(pf4.w + pw.w) * wu4.w;
        } else {
            unsigned long long x01 = f2add(pfp01, pk2(pw.x, pw.y));
            unsigned long long x23 = f2add(pfp23, pk2(pw.z, pw.w));
            unsigned long long t01 = f2mul(x01, x01);
            unsigned long long t23 = f2mul(x23, x23);
            unsigned long long p01 = f2fma(t01, C7, C5);
            unsigned long long p23 = f2fma(t23, C7, C5);
            p01 = f2fma(t01, p01, C3);
            p23 = f2fma(t23, p23, C3);
            p01 = f2fma(t01, p01, ONE);
            p23 = f2fma(t23, p23, ONE);
            unsigned long long y01 = f2mul(x01, p01);
            unsigned long long y23 = f2mul(x23, p23);
            unsigned long long acc = f2mul(y01, wup01);
            acc = f2fma(y23, wup23, acc);
            float a0, a1; upk2(acc, a0, a1);
            s = a0 + a1;
        }
        s += __shfl_xor_sync(0xffffffffu, s, 8);
        s += __shfl_xor_sync(0xffffffffu, s, 4);
        s += __shfl_xor_sync(0xffffffffu, s, 2);
        s += __shfl_xor_sync(0xffffffffu, s, 1);
        if (valid && lane4 == 0) {
            float e = expf(s);
            s_elist[mb] = e;
            wsum += e;
        }
    }
    #pragma unroll
    for (int off = 16; off > 0; off >>= 1)
        wsum += __shfl_xor_sync(0xffffffffu, wsum, off);
    if (lane == 0) s_wsum[wid] = wsum;
    __syncthreads();
    if (tid == 0) {
        float ss = 0.f;
        #pragma unroll
        for (int w = 0; w < 8; w++) ss += s_wsum[w];
        s_inv = (ss > 0.f) ? (1.0f / ss) : 1.0f;
    }
    __syncthreads();

    // ---- Phase C: context accumulation, 4-way unrolled (MLP=4)
    {
        const int g = tid >> 6;
        const int k = tid & 63;
        float a0 = 0.f, a1 = 0.f, a2 = 0.f, a3 = 0.f;
        int m = g;
        for (; m + 12 < cnt; m += 16) {
            a0 += s_elist[m]      * __ldg(&g_full[(int)s_jlist[m]      * Dn + k]);
            a1 += s_elist[m + 4]  * __ldg(&g_full[(int)s_jlist[m + 4]  * Dn + k]);
            a2 += s_elist[m + 8]  * __ldg(&g_full[(int)s_jlist[m + 8]  * Dn + k]);
            a3 += s_elist[m + 12] * __ldg(&g_full[(int)s_jlist[m + 12] * Dn + k]);
        }
        for (; m < cnt; m += 4)
            a0 += s_elist[m] * __ldg(&g_full[(int)s_jlist[m] * Dn + k]);
        s_part[g][k] = (a0 + a1) + (a2 + a3);
        __syncthreads();
        if (tid < Dn)
            g_ctx[i * Dn + tid] = (s_part[0][tid] + s_part[1][tid] +
                                   s_part[2][tid] + s_part[3][tid]) * s_inv;
    }
}

// ---------------------------------------------------------------------------
// Kernel 3: out = values @ ctx  [4096,500]@[500,64] -> [4096,64]
// 256 blocks x 16 rows; thread = 1 row x 4 cols (f32x2 FFMA).
// ---------------------------------------------------------------------------
#define TFk 50
__global__ __launch_bounds__(256) void k3_out(const float* __restrict__ values,
                                              float* __restrict__ out)
{
    __shared__ __align__(16) float s_val[16][TFk];
    __shared__ __align__(16) float s_ctx[TFk][Dn];

    const int tid  = threadIdx.x;
    const int tx   = tid & 15;
    const int ty   = tid >> 4;
    const int col0 = tx * 4;
    const int row  = blockIdx.x * 16 + ty;

    unsigned long long a0 = 0ull, a1 = 0ull;

    for (int f0 = 0; f0 < Fn; f0 += TFk) {
        for (int idx = tid; idx < 16 * TFk; idx += 256) {
            int r = idx / TFk, f = idx % TFk;
            s_val[r][f] = values[(size_t)(blockIdx.x * 16 + r) * Fn + f0 + f];
        }
        for (int idx = tid; idx < TFk * Dn; idx += 256) {
            int f = idx >> 6, c = idx & 63;
            s_ctx[f][c] = g_ctx[(f0 + f) * Dn + c];
        }
        __syncthreads();

        #pragma unroll
        for (int f = 0; f < TFk; f++) {
            float v = s_val[ty][f];
            unsigned long long vp = pk2(v, v);
            const unsigned long long* cp =
                reinterpret_cast<const unsigned long long*>(&s_ctx[f][col0]);
            a0 = f2fma(vp, cp[0], a0);
            a1 = f2fma(vp, cp[1], a1);
        }
        __syncthreads();
    }

    float a, b, c, d;
    upk2(a0, a, b); upk2(a1, c, d);
    *reinterpret_cast<float4*>(&out[(size_t)row * Dn + col0]) =
        make_float4(a, b, c, d);
}

// ---------------------------------------------------------------------------
extern "C" void kernel_launch(void* const* d_in, const int* in_sizes, int n_in,
                              void* d_out, int out_size)
{
    const float* values   = (const float*)d_in[0];   // [4096,500]
    const float* feat_emb = (const float*)d_in[1];   // [500,64]
    const float* hid_emb  = (const float*)d_in[2];   // [2000,64]
    const float* Ww       = (const float*)d_in[3];   // [128,64]
    const float* bw       = (const float*)d_in[4];   // [64]
    const float* Wu       = (const float*)d_in[5];   // [64,1]
    const float* mask     = (const float*)d_in[6];   // [500,2500,1]
    float* out            = (float*)d_out;           // [4096,64]

    k1_preproj<<<189, 256>>>(feat_emb, hid_emb, Ww, bw);
    k2_attn<<<Fn, 256>>>(mask, Wu);
    k3_out<<<Bn / 16, 256>>>(values, out);
}